// round 15
// baseline (speedup 1.0000x reference)
#include <cuda_runtime.h>
#include <math.h>
#include <float.h>

#define DIN   784
#define DH    512
#define DOUT  10
#define BATCH 256

#define KC    8        // k-chunks (split-K)
#define KCH   98       // DIN / KC

#define GEMM_BLOCKS 512
#define PREP_BLOCKS 16
#define TOTAL_BLOCKS (GEMM_BLOCKS + PREP_BLOCKS)   // 528 = 4 * 132

#define AS_SZ  (64 * KCH)       // 6272 floats, natural [b][k]
#define BPAD   36
#define B_SZ   (KCH * BPAD)     // 3528 floats, [k][h] (32h + pad)
#define SMEM_FLOATS (AS_SZ + 2 * B_SZ)      // 13328
#define SMEM_BYTES  (SMEM_FLOATS * 4)       // 53312 -> 4 blocks/SM

#define TRI_N 55
#define NACC  75       // 55 mid + 10 amu + 10 aq

// ---------------- device scratch ----------------
__device__ __align__(16) float g_pmu[KC * BATCH * DH];
__device__ __align__(16) float g_pq [KC * BATCH * DH];
__device__ __align__(16) float g_Ws2[DOUT * DH];
__device__ __align__(16) float g_w2t[DOUT * DH];
__device__ float g_spb1[DH];
__device__ float g_spb2[DOUT];
__device__ float g_klpartA[128];
__device__ float g_klpartB[16];

// ---------------- softplus: fast poly for x < -1, exact fallback ----------------
__device__ __forceinline__ float sp_pair(float x, float& lsp) {
    if (x < -1.0f) {
        float u = __expf(x);
        float P = 1.0f + u * (-0.5f + u * (0.33333334f + u * (-0.25f +
                  u * (0.2f + u * (-0.16666667f + u * 0.14285715f)))));
        float d = P - 1.0f;
        float lp = d * (1.0f + d * (-0.5f + d * (0.33333334f + d * (-0.25f))));
        lsp = x + lp;
        return u * P;
    } else {
        float sp = logf(1.0f + expf(x));
        lsp = logf(sp);
        return sp;
    }
}
__device__ __forceinline__ float sp_only(float x) {
    if (x < -1.0f) {
        float u = __expf(x);
        float P = 1.0f + u * (-0.5f + u * (0.33333334f + u * (-0.25f +
                  u * (0.2f + u * (-0.16666667f + u * 0.14285715f)))));
        return u * P;
    }
    return logf(1.0f + expf(x));
}

// ---------------- K1 MEGA: 512 GEMM blocks (64b x 32h x 98k, 4/SM) + 16 prep ----------------
__global__ __launch_bounds__(256) void k1_mega(const float* __restrict__ x,
                                               const float* __restrict__ w_mu1,
                                               const float* __restrict__ w_sigma1,
                                               const float* __restrict__ b_sigma1,
                                               const float* __restrict__ w_mu2,
                                               const float* __restrict__ w_sigma2,
                                               const float* __restrict__ b_sigma2) {
    extern __shared__ float smem[];
    __shared__ float red[8];
    const int tid = threadIdx.x;
    const int id = blockIdx.x;

    if (id >= GEMM_BLOCKS) {
        // ---- prep role (16 blocks) ----
        const int pid = id - GEMM_BLOCKS;
        float acc = 0.f;
        for (int i = pid * 256 + tid; i < DOUT * DH; i += 16 * 256) {
            float lsp;
            float sp = sp_pair(w_sigma2[i], lsp);
            g_Ws2[i] = sp;
            acc += sp - lsp;
            float v = w_mu2[i];
            acc += v * v;
            g_w2t[(i % DOUT) * DH + (i / DOUT)] = v;
        }
        if (pid == 0) {
            g_spb1[tid]       = sp_only(b_sigma1[tid]);
            g_spb1[tid + 256] = sp_only(b_sigma1[tid + 256]);
            if (tid < DOUT) g_spb2[tid] = sp_only(b_sigma2[tid]);
        }
        #pragma unroll
        for (int s = 16; s; s >>= 1) acc += __shfl_xor_sync(0xffffffffu, acc, s);
        if ((tid & 31) == 0) red[tid >> 5] = acc;
        __syncthreads();
        if (tid == 0) {
            float t = 0.f;
            #pragma unroll
            for (int w = 0; w < 8; w++) t += red[w];
            g_klpartB[pid] = t;
        }
        return;
    }

    // ---- GEMM role ----
    float* As  = smem;              // [b][k] natural, 64 x 98
    float* B1s = smem + AS_SZ;      // [k][h], 98 x 36 (32h used)
    float* B2s = B1s + B_SZ;        // [k][h] softplus'd

    const int ht = id >> 5;                 // 0..15
    const int bt = (id >> 3) & 3;           // 0..3
    const int kc = id & 7;                  // 0..7
    const int n0 = ht * 32;
    const int b0 = bt * 64;
    const int ks = kc * KCH;
    const bool do_kl = (bt == 0);

    float klacc = 0.f;

    // A: x[b][k] natural, float2 along k (64 x 49 pairs)
    for (int i = tid; i < 64 * 49; i += 256) {
        int r = i / 49, c = i % 49;
        *(float2*)&As[r * KCH + c * 2] =
            *(const float2*)&x[(b0 + r) * DIN + ks + c * 2];
    }
    // B1: w_mu1[k][h] natural, coalesced float4 (98 x 8 quads); fold sum-of-squares
    for (int i = tid; i < KCH * 8; i += 256) {
        int r = i >> 3, c = i & 7;
        float4 v = *(const float4*)&w_mu1[(ks + r) * DH + n0 + c * 4];
        *(float4*)&B1s[r * BPAD + c * 4] = v;
        if (do_kl) klacc += v.x * v.x + v.y * v.y + v.z * v.z + v.w * v.w;
    }
    // B2: softplus(w_sigma1[h][k]) transposed into [k][h] (32h x 49 k-pairs)
    for (int i = tid; i < 32 * 49; i += 256) {
        int h = i & 31, kq = i >> 5;            // kq = k pair index (0..48)
        float2 v = *(const float2*)&w_sigma1[(n0 + h) * DIN + ks + kq * 2];
        float l0, l1;
        float s0 = sp_pair(v.x, l0);
        float s1 = sp_pair(v.y, l1);
        if (do_kl) klacc += (s0 - l0) + (s1 - l1);
        B2s[(kq * 2 + 0) * BPAD + h] = s0;
        B2s[(kq * 2 + 1) * BPAD + h] = s1;
    }
    if (do_kl) {
        #pragma unroll
        for (int s = 16; s; s >>= 1) klacc += __shfl_xor_sync(0xffffffffu, klacc, s);
        if ((tid & 31) == 0) red[tid >> 5] = klacc;
    }
    __syncthreads();
    if (do_kl && tid == 0) {
        float t = 0.f;
        #pragma unroll
        for (int w = 0; w < 8; w++) t += red[w];
        g_klpartA[ht * 8 + kc] = t;
    }

    // ---- compute: 2b x 4h microtile, scalar FFMA, 98 straight kk ----
    const int tx = tid & 7;            // h quad (x4 = 32 h)
    const int ty = tid >> 3;           // b pair (x2 = 64 b)

    float mu[2][4] = {}, qq[2][4] = {};
    const float* ap = &As[(ty * 2) * KCH];

    #pragma unroll 7
    for (int kk = 0; kk < KCH; kk++) {
        float a0 = ap[kk];
        float a1 = ap[KCH + kk];
        float4 b1 = *(const float4*)&B1s[kk * BPAD + tx * 4];
        float4 b2 = *(const float4*)&B2s[kk * BPAD + tx * 4];
        float q0 = a0 * a0, q1 = a1 * a1;
        mu[0][0] += a0 * b1.x; mu[0][1] += a0 * b1.y;
        mu[0][2] += a0 * b1.z; mu[0][3] += a0 * b1.w;
        mu[1][0] += a1 * b1.x; mu[1][1] += a1 * b1.y;
        mu[1][2] += a1 * b1.z; mu[1][3] += a1 * b1.w;
        qq[0][0] += q0 * b2.x; qq[0][1] += q0 * b2.y;
        qq[0][2] += q0 * b2.z; qq[0][3] += q0 * b2.w;
        qq[1][0] += q1 * b2.x; qq[1][1] += q1 * b2.y;
        qq[1][2] += q1 * b2.z; qq[1][3] += q1 * b2.w;
    }

    // ---- epilogue: split-K partials ----
    #pragma unroll
    for (int r = 0; r < 2; r++) {
        int b = b0 + ty * 2 + r;
        float4 m = make_float4(mu[r][0], mu[r][1], mu[r][2], mu[r][3]);
        float4 q = make_float4(qq[r][0], qq[r][1], qq[r][2], qq[r][3]);
        *(float4*)&g_pmu[(kc * BATCH + b) * DH + n0 + tx * 4] = m;
        *(float4*)&g_pq [(kc * BATCH + b) * DH + n0 + tx * 4] = q;
    }
}

// ---------------- s2 recompute from partials (cross-batch trace gather) ----------------
__device__ __forceinline__ float s2_at(int m, int h, const float* __restrict__ b_mu1) {
    float mu = b_mu1[h];
    #pragma unroll
    for (int c = 0; c < KC; c++) mu += g_pmu[(c * BATCH + m) * DH + h];
    if (mu <= 0.f) return 0.f;
    float q = g_spb1[h];
    #pragma unroll
    for (int c = 0; c < KC; c++) q += g_pq[(c * BATCH + m) * DH + h];
    return q;
}

// ---------------- per-warp accumulator strip over a 128-h quarter, float2 ----------------
template<int LO, int HI>
__device__ __forceinline__ void accum_strip(const float* __restrict__ m2s,
                                            const float* __restrict__ s2s,
                                            const float* __restrict__ w2s,
                                            float* __restrict__ wp,
                                            int h0, int lane) {
    float acc[HI - LO];
    #pragma unroll
    for (int j = 0; j < HI - LO; j++) acc[j] = 0.f;

    #pragma unroll
    for (int t = 0; t < 2; t++) {
        int h = h0 + t * 64 + lane * 2;
        float2 m = *(const float2*)&m2s[h];
        float2 s = *(const float2*)&s2s[h];
        float2 mm = make_float2(m.x * m.x, m.y * m.y);
        float2 w[DOUT], sw[DOUT];
        #pragma unroll
        for (int o = 0; o < DOUT; o++) w[o] = *(const float2*)&w2s[o * DH + h];
        #pragma unroll
        for (int o = 0; o < DOUT; o++) {
            sw[o].x = s.x * w[o].x;
            sw[o].y = s.y * w[o].y;
        }
        {
            int e = 0;
            #pragma unroll
            for (int o = 0; o < DOUT; o++)
                #pragma unroll
                for (int p = o; p < DOUT; p++) {
                    if (e >= LO && e < HI)
                        acc[e - LO] += w[p].x * sw[o].x + w[p].y * sw[o].y;
                    e++;
                }
        }
        #pragma unroll
        for (int o = 0; o < DOUT; o++)
            if (TRI_N + o >= LO && TRI_N + o < HI)
                acc[TRI_N + o - LO] += w[o].x * m.x + w[o].y * m.y;
        #pragma unroll
        for (int o = 0; o < DOUT; o++)
            if (65 + o >= LO && 65 + o < HI) {
                float2 ws = __ldg((const float2*)&g_Ws2[o * DH + h]);
                acc[65 + o - LO] += ws.x * mm.x + ws.y * mm.y;
            }
    }

    #pragma unroll
    for (int s = 16; s; s >>= 1)
        #pragma unroll
        for (int j = 0; j < HI - LO; j++)
            acc[j] += __shfl_xor_sync(0xffffffffu, acc[j], s);

    #pragma unroll
    for (int j = 0; j < HI - LO; j++)
        if (lane == j) wp[LO + j] = acc[j];
}

// ---------------- K2: one block per batch, 512 threads ----------------
__global__ __launch_bounds__(512) void k2_layer2(const float* __restrict__ b_mu1,
                                                 const float* __restrict__ b_mu2,
                                                 float* __restrict__ out) {
    __shared__ float m2s[DH], s2s[DH];
    __shared__ float w2s[DOUT * DH];
    __shared__ float wp[4][NACC];
    __shared__ float S[240];
    __shared__ float saq[DOUT];

    const int tid = threadIdx.x;
    const int warp = tid >> 5, lane = tid & 31;
    const int b = blockIdx.x;
    const int SZ = BATCH * DH;

    // ---- phase 1: combine split-K partials + bias + ReLU ----
    {
        int h = tid;
        int idx = b * DH + h;
        float mu = __ldg(b_mu1 + h);
        #pragma unroll
        for (int c = 0; c < KC; c++) mu += g_pmu[c * SZ + idx];
        float q = g_spb1[h];
        #pragma unroll
        for (int c = 0; c < KC; c++) q += g_pq[c * SZ + idx];
        bool gate = (mu > 0.f);
        m2s[h] = gate ? mu : 0.f;
        s2s[h] = gate ? q : 0.f;
    }
    for (int i = tid; i < DOUT * DH / 4; i += 512)
        *(float4*)&w2s[i * 4] = *(const float4*)&g_w2t[i * 4];
    __syncthreads();

    // ---- phase 2: 16 warps = 4 accumulator strips x 4 h-quarters ----
    {
        const int quarter = warp >> 2;
        const int h0 = quarter * 128;
        float* wpp = wp[quarter];
        switch (warp & 3) {
            case 0: accum_strip< 0, 19>(m2s, s2s, w2s, wpp, h0, lane); break;
            case 1: accum_strip<19, 38>(m2s, s2s, w2s, wpp, h0, lane); break;
            case 2: accum_strip<38, 57>(m2s, s2s, w2s, wpp, h0, lane); break;
            default: accum_strip<57, 75>(m2s, s2s, w2s, wpp, h0, lane); break;
        }
    }
    __syncthreads();

    // ---- assembly ----
    if (tid < NACC) {
        float v = (wp[0][tid] + wp[1][tid]) + (wp[2][tid] + wp[3][tid]);
        if (tid < TRI_N) {
            int o = 0, rem = tid;
            #pragma unroll
            for (int r = 0; r < DOUT; r++) {
                if (rem >= DOUT - r && o == r) { rem -= DOUT - r; o = r + 1; }
            }
            int p = o + rem;
            S[o * DOUT + p] = v;
            S[p * DOUT + o] = v;
        } else if (tid < 65) {
            int o = tid - TRI_N;
            S[210 + o] = v + __ldg(b_mu2 + o);
        } else {
            saq[tid - 65] = v;
        }
    }
    __syncthreads();
    if (tid < DOUT) {
        // faithful replication of reference's flattened-view trace term
        int n  = DOUT * b + tid;
        int qn = n >> 8;
        int mn = n & 255;
        float trf = g_Ws2[qn * DH + 2 * mn]     * s2_at(mn, mn, b_mu1)
                  + g_Ws2[qn * DH + 2 * mn + 1] * s2_at(mn, 256 + mn, b_mu1);
        S[tid * DOUT + tid] += trf + saq[tid] + g_spb2[tid];
    }
    __syncthreads();

    // ---- softmax + sandwich (warp 0) ----
    if (warp == 0) {
        float v = (lane < DOUT) ? S[210 + lane] : -FLT_MAX;
        float mx = v;
        #pragma unroll
        for (int s = 16; s; s >>= 1) mx = fmaxf(mx, __shfl_xor_sync(0xffffffffu, mx, s));
        float e = (lane < DOUT) ? expf(v - mx) : 0.f;
        float sm = e;
        #pragma unroll
        for (int s = 16; s; s >>= 1) sm += __shfl_xor_sync(0xffffffffu, sm, s);
        if (lane < DOUT) {
            float p = e / sm;
            S[200 + lane] = p;
            out[b * DOUT + lane] = p;
        }
        __syncwarp();

        if (lane < DOUT) {
            float a = 0.f;
            #pragma unroll
            for (int j = 0; j < DOUT; j++) a += S[200 + j] * S[j * DOUT + lane];
            S[220 + lane] = a;
        }
        __syncwarp();
        for (int e2 = lane; e2 < DOUT * DOUT; e2 += 32) {
            int i = e2 / DOUT, k = e2 % DOUT;
            S[100 + e2] = S[200 + i] * (S[e2] - S[220 + k]);
        }
        __syncwarp();
        if (lane < DOUT) {
            float a = 0.f;
            #pragma unroll
            for (int k = 0; k < DOUT; k++) a += S[100 + lane * DOUT + k] * S[200 + k];
            S[230 + lane] = a;
        }
        __syncwarp();
        for (int e2 = lane; e2 < DOUT * DOUT; e2 += 32) {
            int i = e2 / DOUT, l = e2 % DOUT;
            out[BATCH * DOUT + b * DOUT * DOUT + e2] = S[200 + l] * (S[100 + e2] - S[230 + i]);
        }
    }
}

// ---------------- K3: KL finalize ----------------
__global__ __launch_bounds__(128) void k3_fin(float* __restrict__ out) {
    __shared__ float kred[4];
    const int tid = threadIdx.x;
    float a = g_klpartA[tid];
    if (tid < 16) a += g_klpartB[tid];
    #pragma unroll
    for (int s = 16; s; s >>= 1) a += __shfl_xor_sync(0xffffffffu, a, s);
    if ((tid & 31) == 0) kred[tid >> 5] = a;
    __syncthreads();
    if (tid == 0)
        out[BATCH * DOUT + BATCH * DOUT * DOUT] =
            0.5f * ((kred[0] + kred[1] + kred[2] + kred[3])
                    - (float)(DH * DIN + DOUT * DH));
}

// ---------------- launch ----------------
extern "C" void kernel_launch(void* const* d_in, const int* in_sizes, int n_in,
                              void* d_out, int out_size) {
    const float* x        = (const float*)d_in[0];
    const float* w_mu1    = (const float*)d_in[1];
    const float* w_sigma1 = (const float*)d_in[2];
    const float* b_mu1    = (const float*)d_in[3];
    const float* b_sigma1 = (const float*)d_in[4];
    const float* w_mu2    = (const float*)d_in[5];
    const float* w_sigma2 = (const float*)d_in[6];
    const float* b_mu2    = (const float*)d_in[7];
    const float* b_sigma2 = (const float*)d_in[8];
    float* out = (float*)d_out;

    cudaFuncSetAttribute(k1_mega, cudaFuncAttributeMaxDynamicSharedMemorySize, SMEM_BYTES);
    k1_mega<<<TOTAL_BLOCKS, 256, SMEM_BYTES>>>(x, w_mu1, w_sigma1, b_sigma1,
                                               w_mu2, w_sigma2, b_sigma2);
    k2_layer2<<<BATCH, 512>>>(b_mu1, b_mu2, out);
    k3_fin<<<1, 128>>>(out);
}

// round 16
// speedup vs baseline: 1.2749x; 1.2749x over previous
#include <cuda_runtime.h>
#include <math.h>
#include <float.h>

#define DIN   784
#define DH    512
#define DOUT  10
#define BATCH 256

#define KC    8        // k-chunks (split-K)
#define KCH   98       // DIN / KC

#define GEMM_BLOCKS 256        // 16 ht x 2 bt x 8 kc
#define PREP_BLOCKS 16
#define TOTAL_BLOCKS (GEMM_BLOCKS + PREP_BLOCKS)

#define ASTR  100              // As row stride (pad 98 -> 100, keeps 16B align)
#define BSTR  36               // B tile row stride (32h + pad)
#define AS_SZ (128 * ASTR)     // 12800 floats
#define B_SZ  (KCH * BSTR)     // 3528 floats
#define SMEM_FLOATS (AS_SZ + 2 * B_SZ)   // 19856
#define SMEM_BYTES  (SMEM_FLOATS * 4)    // 79424 -> 2 blocks/SM

#define TRI_N 55
#define NACC  75       // 55 mid + 10 amu + 10 aq

// ---------------- device scratch ----------------
__device__ __align__(16) float g_pmu[KC * BATCH * DH];
__device__ __align__(16) float g_pq [KC * BATCH * DH];
__device__ __align__(16) float g_Ws2[DOUT * DH];
__device__ __align__(16) float g_w2t[DOUT * DH];
__device__ float g_spb1[DH];
__device__ float g_spb2[DOUT];
__device__ float g_klpartA[128];
__device__ float g_klpartB[16];

// ---------------- softplus: fast poly for x < -1, exact fallback ----------------
__device__ __forceinline__ float sp_pair(float x, float& lsp) {
    if (x < -1.0f) {
        float u = __expf(x);
        float P = 1.0f + u * (-0.5f + u * (0.33333334f + u * (-0.25f +
                  u * (0.2f + u * (-0.16666667f + u * 0.14285715f)))));
        float d = P - 1.0f;
        float lp = d * (1.0f + d * (-0.5f + d * (0.33333334f + d * (-0.25f))));
        lsp = x + lp;
        return u * P;
    } else {
        float sp = logf(1.0f + expf(x));
        lsp = logf(sp);
        return sp;
    }
}
__device__ __forceinline__ float sp_only(float x) {
    if (x < -1.0f) {
        float u = __expf(x);
        float P = 1.0f + u * (-0.5f + u * (0.33333334f + u * (-0.25f +
                  u * (0.2f + u * (-0.16666667f + u * 0.14285715f)))));
        return u * P;
    }
    return logf(1.0f + expf(x));
}

// ---------------- K1 MEGA: 256 GEMM blocks (128b x 32h x 98k, 2/SM) + 16 prep ----------------
// Register-blocked mainloop: B-tile chunk cached in registers, 12 LDS per 144 FMA.
__global__ __launch_bounds__(256) void k1_mega(const float* __restrict__ x,
                                               const float* __restrict__ w_mu1,
                                               const float* __restrict__ w_sigma1,
                                               const float* __restrict__ b_sigma1,
                                               const float* __restrict__ w_mu2,
                                               const float* __restrict__ w_sigma2,
                                               const float* __restrict__ b_sigma2) {
    extern __shared__ float smem[];
    __shared__ float red[8];
    const int tid = threadIdx.x;
    const int id = blockIdx.x;

    if (id >= GEMM_BLOCKS) {
        // ---- prep role (16 blocks) ----
        const int pid = id - GEMM_BLOCKS;
        float acc = 0.f;
        for (int i = pid * 256 + tid; i < DOUT * DH; i += 16 * 256) {
            float lsp;
            float sp = sp_pair(w_sigma2[i], lsp);
            g_Ws2[i] = sp;
            acc += sp - lsp;
            float v = w_mu2[i];
            acc += v * v;
            g_w2t[(i % DOUT) * DH + (i / DOUT)] = v;
        }
        if (pid == 0) {
            g_spb1[tid]       = sp_only(b_sigma1[tid]);
            g_spb1[tid + 256] = sp_only(b_sigma1[tid + 256]);
            if (tid < DOUT) g_spb2[tid] = sp_only(b_sigma2[tid]);
        }
        #pragma unroll
        for (int s = 16; s; s >>= 1) acc += __shfl_xor_sync(0xffffffffu, acc, s);
        if ((tid & 31) == 0) red[tid >> 5] = acc;
        __syncthreads();
        if (tid == 0) {
            float t = 0.f;
            #pragma unroll
            for (int w = 0; w < 8; w++) t += red[w];
            g_klpartB[pid] = t;
        }
        return;
    }

    // ---- GEMM role ----
    float* As  = smem;              // [b][k], 128 x 100 (98 used)
    float* B1s = smem + AS_SZ;      // [k][h], 98 x 36 (32 used)
    float* B2s = B1s + B_SZ;        // [k][h] softplus'd

    const int ht = id >> 4;                 // 0..15
    const int bt = (id >> 3) & 1;           // 0..1
    const int kc = id & 7;                  // 0..7
    const int n0 = ht * 32;
    const int b0 = bt * 128;
    const int ks = kc * KCH;
    const bool do_kl = (bt == 0);

    float klacc = 0.f;

    // A: x[b][k] natural, float2 along k (128 x 49 pairs)
    for (int i = tid; i < 128 * 49; i += 256) {
        int r = i / 49, c = i % 49;
        *(float2*)&As[r * ASTR + c * 2] =
            *(const float2*)&x[(b0 + r) * DIN + ks + c * 2];
    }
    // B1: w_mu1[k][h] natural, coalesced float4 (98 x 8 quads); fold sum-of-squares
    for (int i = tid; i < KCH * 8; i += 256) {
        int r = i >> 3, c = i & 7;
        float4 v = *(const float4*)&w_mu1[(ks + r) * DH + n0 + c * 4];
        *(float4*)&B1s[r * BSTR + c * 4] = v;
        if (do_kl) klacc += v.x * v.x + v.y * v.y + v.z * v.z + v.w * v.w;
    }
    // B2: softplus(w_sigma1[h][k]) transposed into [k][h] (32h x 49 k-pairs)
    for (int i = tid; i < 32 * 49; i += 256) {
        int h = i & 31, kq = i >> 5;
        float2 v = *(const float2*)&w_sigma1[(n0 + h) * DIN + ks + kq * 2];
        float l0, l1;
        float s0 = sp_pair(v.x, l0);
        float s1 = sp_pair(v.y, l1);
        if (do_kl) klacc += (s0 - l0) + (s1 - l1);
        B2s[(kq * 2 + 0) * BSTR + h] = s0;
        B2s[(kq * 2 + 1) * BSTR + h] = s1;
    }
    if (do_kl) {
        #pragma unroll
        for (int s = 16; s; s >>= 1) klacc += __shfl_xor_sync(0xffffffffu, klacc, s);
        if ((tid & 31) == 0) red[tid >> 5] = klacc;
    }
    __syncthreads();
    if (do_kl && tid == 0) {
        float t = 0.f;
        #pragma unroll
        for (int w = 0; w < 8; w++) t += red[w];
        g_klpartA[ht * 8 + kc] = t;
    }

    // ---- mainloop: 4b x 4h microtile, register-cached B chunks of 4 k ----
    const int tx = tid & 7;            // h quad (x4 = 32 h)
    const int ty = tid >> 3;           // b quad (x4 = 128 b)

    float mu[4][4] = {}, qq[4][4] = {};
    const float* ap = &As[(ty * 4) * ASTR];

    #pragma unroll 2
    for (int c = 0; c < 24; c++) {             // 24 chunks x 4k = 96
        const int k0 = c * 4;
        float4 b1r[4], b2r[4];
        #pragma unroll
        for (int j = 0; j < 4; j++) {
            b1r[j] = *(const float4*)&B1s[(k0 + j) * BSTR + tx * 4];
            b2r[j] = *(const float4*)&B2s[(k0 + j) * BSTR + tx * 4];
        }
        #pragma unroll
        for (int r = 0; r < 4; r++) {
            float4 av = *(const float4*)&ap[r * ASTR + k0];
            float a[4] = {av.x, av.y, av.z, av.w};
            #pragma unroll
            for (int j = 0; j < 4; j++) {
                float s = a[j] * a[j];
                mu[r][0] += a[j] * b1r[j].x; mu[r][1] += a[j] * b1r[j].y;
                mu[r][2] += a[j] * b1r[j].z; mu[r][3] += a[j] * b1r[j].w;
                qq[r][0] += s * b2r[j].x;    qq[r][1] += s * b2r[j].y;
                qq[r][2] += s * b2r[j].z;    qq[r][3] += s * b2r[j].w;
            }
        }
    }
    // remainder k = 96, 97
    #pragma unroll
    for (int j = 0; j < 2; j++) {
        const int kk = 96 + j;
        float4 b1j = *(const float4*)&B1s[kk * BSTR + tx * 4];
        float4 b2j = *(const float4*)&B2s[kk * BSTR + tx * 4];
        #pragma unroll
        for (int r = 0; r < 4; r++) {
            float a = ap[r * ASTR + kk];
            float s = a * a;
            mu[r][0] += a * b1j.x; mu[r][1] += a * b1j.y;
            mu[r][2] += a * b1j.z; mu[r][3] += a * b1j.w;
            qq[r][0] += s * b2j.x; qq[r][1] += s * b2j.y;
            qq[r][2] += s * b2j.z; qq[r][3] += s * b2j.w;
        }
    }

    // ---- epilogue: split-K partials ----
    #pragma unroll
    for (int r = 0; r < 4; r++) {
        int b = b0 + ty * 4 + r;
        float4 m = make_float4(mu[r][0], mu[r][1], mu[r][2], mu[r][3]);
        float4 q = make_float4(qq[r][0], qq[r][1], qq[r][2], qq[r][3]);
        *(float4*)&g_pmu[(kc * BATCH + b) * DH + n0 + tx * 4] = m;
        *(float4*)&g_pq [(kc * BATCH + b) * DH + n0 + tx * 4] = q;
    }
}

// ---------------- s2 recompute from partials (cross-batch trace gather) ----------------
__device__ __forceinline__ float s2_at(int m, int h, const float* __restrict__ b_mu1) {
    float mu = b_mu1[h];
    #pragma unroll
    for (int c = 0; c < KC; c++) mu += g_pmu[(c * BATCH + m) * DH + h];
    if (mu <= 0.f) return 0.f;
    float q = g_spb1[h];
    #pragma unroll
    for (int c = 0; c < KC; c++) q += g_pq[(c * BATCH + m) * DH + h];
    return q;
}

// ---------------- per-warp accumulator strip over a 128-h quarter, float2 ----------------
template<int LO, int HI>
__device__ __forceinline__ void accum_strip(const float* __restrict__ m2s,
                                            const float* __restrict__ s2s,
                                            const float* __restrict__ w2s,
                                            float* __restrict__ wp,
                                            int h0, int lane) {
    float acc[HI - LO];
    #pragma unroll
    for (int j = 0; j < HI - LO; j++) acc[j] = 0.f;

    #pragma unroll
    for (int t = 0; t < 2; t++) {
        int h = h0 + t * 64 + lane * 2;
        float2 m = *(const float2*)&m2s[h];
        float2 s = *(const float2*)&s2s[h];
        float2 mm = make_float2(m.x * m.x, m.y * m.y);
        float2 w[DOUT], sw[DOUT];
        #pragma unroll
        for (int o = 0; o < DOUT; o++) w[o] = *(const float2*)&w2s[o * DH + h];
        #pragma unroll
        for (int o = 0; o < DOUT; o++) {
            sw[o].x = s.x * w[o].x;
            sw[o].y = s.y * w[o].y;
        }
        {
            int e = 0;
            #pragma unroll
            for (int o = 0; o < DOUT; o++)
                #pragma unroll
                for (int p = o; p < DOUT; p++) {
                    if (e >= LO && e < HI)
                        acc[e - LO] += w[p].x * sw[o].x + w[p].y * sw[o].y;
                    e++;
                }
        }
        #pragma unroll
        for (int o = 0; o < DOUT; o++)
            if (TRI_N + o >= LO && TRI_N + o < HI)
                acc[TRI_N + o - LO] += w[o].x * m.x + w[o].y * m.y;
        #pragma unroll
        for (int o = 0; o < DOUT; o++)
            if (65 + o >= LO && 65 + o < HI) {
                float2 ws = __ldg((const float2*)&g_Ws2[o * DH + h]);
                acc[65 + o - LO] += ws.x * mm.x + ws.y * mm.y;
            }
    }

    #pragma unroll
    for (int s = 16; s; s >>= 1)
        #pragma unroll
        for (int j = 0; j < HI - LO; j++)
            acc[j] += __shfl_xor_sync(0xffffffffu, acc[j], s);

    #pragma unroll
    for (int j = 0; j < HI - LO; j++)
        if (lane == j) wp[LO + j] = acc[j];
}

// ---------------- K2: one block per batch, 512 threads; KL finalize in block 0 ----------------
__global__ __launch_bounds__(512) void k2_layer2(const float* __restrict__ b_mu1,
                                                 const float* __restrict__ b_mu2,
                                                 float* __restrict__ out) {
    __shared__ float m2s[DH], s2s[DH];
    __shared__ float w2s[DOUT * DH];
    __shared__ float wp[4][NACC];
    __shared__ float S[240];
    __shared__ float saq[DOUT];

    const int tid = threadIdx.x;
    const int warp = tid >> 5, lane = tid & 31;
    const int b = blockIdx.x;
    const int SZ = BATCH * DH;

    // ---- phase 1: combine split-K partials + bias + ReLU ----
    {
        int h = tid;
        int idx = b * DH + h;
        float mu = __ldg(b_mu1 + h);
        #pragma unroll
        for (int c = 0; c < KC; c++) mu += g_pmu[c * SZ + idx];
        float q = g_spb1[h];
        #pragma unroll
        for (int c = 0; c < KC; c++) q += g_pq[c * SZ + idx];
        bool gate = (mu > 0.f);
        m2s[h] = gate ? mu : 0.f;
        s2s[h] = gate ? q : 0.f;
    }
    for (int i = tid; i < DOUT * DH / 4; i += 512)
        *(float4*)&w2s[i * 4] = *(const float4*)&g_w2t[i * 4];
    __syncthreads();

    // ---- phase 2: 16 warps = 4 accumulator strips x 4 h-quarters ----
    {
        const int quarter = warp >> 2;
        const int h0 = quarter * 128;
        float* wpp = wp[quarter];
        switch (warp & 3) {
            case 0: accum_strip< 0, 19>(m2s, s2s, w2s, wpp, h0, lane); break;
            case 1: accum_strip<19, 38>(m2s, s2s, w2s, wpp, h0, lane); break;
            case 2: accum_strip<38, 57>(m2s, s2s, w2s, wpp, h0, lane); break;
            default: accum_strip<57, 75>(m2s, s2s, w2s, wpp, h0, lane); break;
        }
    }
    __syncthreads();

    // ---- assembly ----
    if (tid < NACC) {
        float v = (wp[0][tid] + wp[1][tid]) + (wp[2][tid] + wp[3][tid]);
        if (tid < TRI_N) {
            int o = 0, rem = tid;
            #pragma unroll
            for (int r = 0; r < DOUT; r++) {
                if (rem >= DOUT - r && o == r) { rem -= DOUT - r; o = r + 1; }
            }
            int p = o + rem;
            S[o * DOUT + p] = v;
            S[p * DOUT + o] = v;
        } else if (tid < 65) {
            int o = tid - TRI_N;
            S[210 + o] = v + __ldg(b_mu2 + o);
        } else {
            saq[tid - 65] = v;
        }
    }
    __syncthreads();
    if (tid < DOUT) {
        // faithful replication of reference's flattened-view trace term
        int n  = DOUT * b + tid;
        int qn = n >> 8;
        int mn = n & 255;
        float trf = g_Ws2[qn * DH + 2 * mn]     * s2_at(mn, mn, b_mu1)
                  + g_Ws2[qn * DH + 2 * mn + 1] * s2_at(mn, 256 + mn, b_mu1);
        S[tid * DOUT + tid] += trf + saq[tid] + g_spb2[tid];
    }
    __syncthreads();

    // ---- softmax + sandwich (warp 0); KL finalize (block 0 warp 1) ----
    if (warp == 0) {
        float v = (lane < DOUT) ? S[210 + lane] : -FLT_MAX;
        float mx = v;
        #pragma unroll
        for (int s = 16; s; s >>= 1) mx = fmaxf(mx, __shfl_xor_sync(0xffffffffu, mx, s));
        float e = (lane < DOUT) ? expf(v - mx) : 0.f;
        float sm = e;
        #pragma unroll
        for (int s = 16; s; s >>= 1) sm += __shfl_xor_sync(0xffffffffu, sm, s);
        if (lane < DOUT) {
            float p = e / sm;
            S[200 + lane] = p;
            out[b * DOUT + lane] = p;
        }
        __syncwarp();

        if (lane < DOUT) {
            float a = 0.f;
            #pragma unroll
            for (int j = 0; j < DOUT; j++) a += S[200 + j] * S[j * DOUT + lane];
            S[220 + lane] = a;
        }
        __syncwarp();
        for (int e2 = lane; e2 < DOUT * DOUT; e2 += 32) {
            int i = e2 / DOUT, k = e2 % DOUT;
            S[100 + e2] = S[200 + i] * (S[e2] - S[220 + k]);
        }
        __syncwarp();
        if (lane < DOUT) {
            float a = 0.f;
            #pragma unroll
            for (int k = 0; k < DOUT; k++) a += S[100 + lane * DOUT + k] * S[200 + k];
            S[230 + lane] = a;
        }
        __syncwarp();
        for (int e2 = lane; e2 < DOUT * DOUT; e2 += 32) {
            int i = e2 / DOUT, l = e2 % DOUT;
            out[BATCH * DOUT + b * DOUT * DOUT + e2] = S[200 + l] * (S[100 + e2] - S[230 + i]);
        }
    } else if (warp == 1 && b == 0) {
        // KL finalize: independent of warp 0's work; inputs ready since k1 completed
        float a = g_klpartA[lane] + g_klpartA[32 + lane]
                + g_klpartA[64 + lane] + g_klpartA[96 + lane];
        if (lane < 16) a += g_klpartB[lane];
        #pragma unroll
        for (int s = 16; s; s >>= 1) a += __shfl_xor_sync(0xffffffffu, a, s);
        if (lane == 0)
            out[BATCH * DOUT + BATCH * DOUT * DOUT] =
                0.5f * (a - (float)(DH * DIN + DOUT * DH));
    }
}

// ---------------- launch ----------------
extern "C" void kernel_launch(void* const* d_in, const int* in_sizes, int n_in,
                              void* d_out, int out_size) {
    const float* x        = (const float*)d_in[0];
    const float* w_mu1    = (const float*)d_in[1];
    const float* w_sigma1 = (const float*)d_in[2];
    const float* b_mu1    = (const float*)d_in[3];
    const float* b_sigma1 = (const float*)d_in[4];
    const float* w_mu2    = (const float*)d_in[5];
    const float* w_sigma2 = (const float*)d_in[6];
    const float* b_mu2    = (const float*)d_in[7];
    const float* b_sigma2 = (const float*)d_in[8];
    float* out = (float*)d_out;

    cudaFuncSetAttribute(k1_mega, cudaFuncAttributeMaxDynamicSharedMemorySize, SMEM_BYTES);
    k1_mega<<<TOTAL_BLOCKS, 256, SMEM_BYTES>>>(x, w_mu1, w_sigma1, b_sigma1,
                                               w_mu2, w_sigma2, b_sigma2);
    k2_layer2<<<BATCH, 512>>>(b_mu1, b_mu2, out);
}